// round 1
// baseline (speedup 1.0000x reference)
#include <cuda_runtime.h>
#include <cuda_fp16.h>

#define BATCH 16
#define SEQ   2048
#define HD    128
#define BM    128
#define BN    128
#define LDSH  (HD + 8)   // 136 halfs per smem row (pad kills bank conflicts)

// fp16 staging buffers (static __device__: no allocation rules violated)
__device__ __align__(16) __half g_q[(size_t)BATCH * SEQ * HD];
__device__ __align__(16) __half g_k[(size_t)BATCH * SEQ * HD];
__device__ __align__(16) __half g_v[(size_t)BATCH * SEQ * HD];

// ---------------------------------------------------------------------------
// fp32 -> fp16 convert (Q pre-scaled by 1/sqrt(D) * log2(e) so softmax = ex2)
// ---------------------------------------------------------------------------
__global__ void cvt_kernel(const float* __restrict__ src, int which, int n4, float scale) {
    __half* dst = (which == 0) ? g_q : (which == 1) ? g_k : g_v;
    int i = blockIdx.x * blockDim.x + threadIdx.x;
    if (i < n4) {
        float4 f = reinterpret_cast<const float4*>(src)[i];
        __half2 h0 = __floats2half2_rn(f.x * scale, f.y * scale);
        __half2 h1 = __floats2half2_rn(f.z * scale, f.w * scale);
        reinterpret_cast<__half2*>(dst)[2 * i + 0] = h0;
        reinterpret_cast<__half2*>(dst)[2 * i + 1] = h1;
    }
}

// ---------------------------------------------------------------------------
// helpers
// ---------------------------------------------------------------------------
__device__ __forceinline__ float ex2(float x) {
    float y;
    asm("ex2.approx.ftz.f32 %0, %1;" : "=f"(y) : "f"(x));
    return y;
}

__device__ __forceinline__ void ldmx4(unsigned& r0, unsigned& r1, unsigned& r2, unsigned& r3,
                                      const __half* p) {
    unsigned a = (unsigned)__cvta_generic_to_shared(p);
    asm volatile("ldmatrix.sync.aligned.m8n8.x4.shared.b16 {%0,%1,%2,%3}, [%4];"
                 : "=r"(r0), "=r"(r1), "=r"(r2), "=r"(r3) : "r"(a));
}

__device__ __forceinline__ void ldmx4t(unsigned& r0, unsigned& r1, unsigned& r2, unsigned& r3,
                                       const __half* p) {
    unsigned a = (unsigned)__cvta_generic_to_shared(p);
    asm volatile("ldmatrix.sync.aligned.m8n8.x4.trans.shared.b16 {%0,%1,%2,%3}, [%4];"
                 : "=r"(r0), "=r"(r1), "=r"(r2), "=r"(r3) : "r"(a));
}

__device__ __forceinline__ void mma16816(float* c, unsigned a0, unsigned a1, unsigned a2,
                                         unsigned a3, unsigned b0, unsigned b1) {
    asm volatile(
        "mma.sync.aligned.m16n8k16.row.col.f32.f16.f16.f32 "
        "{%0,%1,%2,%3}, {%4,%5,%6,%7}, {%8,%9}, {%0,%1,%2,%3};"
        : "+f"(c[0]), "+f"(c[1]), "+f"(c[2]), "+f"(c[3])
        : "r"(a0), "r"(a1), "r"(a2), "r"(a3), "r"(b0), "r"(b1));
}

__device__ __forceinline__ unsigned packh2(float a, float b) {
    __half2 h = __floats2half2_rn(a, b);
    return *reinterpret_cast<unsigned*>(&h);
}

// ---------------------------------------------------------------------------
// fused attention: pass1 exact (m,l) over all K, pass2 recompute S, write
// normalized attention, accumulate O = P @ V.  One CTA = 128 q rows.
// ---------------------------------------------------------------------------
__global__ __launch_bounds__(256, 1)
void attn_kernel(float* __restrict__ ctx, float* __restrict__ attn) {
    extern __shared__ __half sm[];
    __half* sQ = sm;                 // BM x LDSH
    __half* sK = sQ + BM * LDSH;     // BN x LDSH
    __half* sV = sK + BN * LDSH;     // BN x LDSH

    const int b = blockIdx.y;
    const int qt = blockIdx.x;
    const int tid = threadIdx.x;
    const int lane = tid & 31;
    const int warp = tid >> 5;
    const int wrow = warp << 4;      // this warp owns 16 q rows

    const __half* Qg = g_q + ((size_t)b * SEQ + (size_t)qt * BM) * HD;
    const __half* Kg = g_k + (size_t)b * SEQ * HD;
    const __half* Vg = g_v + (size_t)b * SEQ * HD;

    // load Q tile once
    #pragma unroll
    for (int i = tid; i < BM * 16; i += 256) {
        int r = i >> 4, c = (i & 15) << 3;
        *reinterpret_cast<uint4*>(sQ + r * LDSH + c) =
            *reinterpret_cast<const uint4*>(Qg + (size_t)r * HD + c);
    }

    // per-thread lane geometry for ldmatrix
    const int aRow = wrow + (lane & 15);
    const int aCol = (lane >> 4) << 3;
    const int bRowOff = ((lane >> 4) << 3) + (lane & 7);
    const int bColOff = ((lane >> 3) & 1) << 3;
    const int vRowOff = lane & 15;
    const int vColOff = (lane >> 4) << 3;

    float m_a = -1e30f, m_b = -1e30f, l_a = 0.f, l_b = 0.f;

    // ------------------------- pass 1: m, l -------------------------------
    for (int kt = 0; kt < 16; kt++) {
        __syncthreads();
        #pragma unroll
        for (int i = tid; i < BN * 16; i += 256) {
            int r = i >> 4, c = (i & 15) << 3;
            *reinterpret_cast<uint4*>(sK + r * LDSH + c) =
                *reinterpret_cast<const uint4*>(Kg + ((size_t)(kt * BN + r)) * HD + c);
        }
        __syncthreads();

        float S[16][4];
        #pragma unroll
        for (int nt = 0; nt < 16; nt++)
            #pragma unroll
            for (int j = 0; j < 4; j++) S[nt][j] = 0.f;

        #pragma unroll 1
        for (int k2 = 0; k2 < 8; k2++) {
            unsigned a0, a1, a2, a3;
            ldmx4(a0, a1, a2, a3, sQ + aRow * LDSH + (k2 << 4) + aCol);
            #pragma unroll
            for (int n2 = 0; n2 < 8; n2++) {
                unsigned b0, b1, b2, b3;
                ldmx4(b0, b1, b2, b3,
                      sK + ((n2 << 4) + bRowOff) * LDSH + (k2 << 4) + bColOff);
                mma16816(S[2 * n2],     a0, a1, a2, a3, b0, b1);
                mma16816(S[2 * n2 + 1], a0, a1, a2, a3, b2, b3);
            }
        }

        float tma = -1e30f, tmb = -1e30f;
        #pragma unroll
        for (int nt = 0; nt < 16; nt++) {
            tma = fmaxf(tma, fmaxf(S[nt][0], S[nt][1]));
            tmb = fmaxf(tmb, fmaxf(S[nt][2], S[nt][3]));
        }
        tma = fmaxf(tma, __shfl_xor_sync(0xffffffffu, tma, 1));
        tma = fmaxf(tma, __shfl_xor_sync(0xffffffffu, tma, 2));
        tmb = fmaxf(tmb, __shfl_xor_sync(0xffffffffu, tmb, 1));
        tmb = fmaxf(tmb, __shfl_xor_sync(0xffffffffu, tmb, 2));

        float nma = fmaxf(m_a, tma), nmb = fmaxf(m_b, tmb);
        float sa = 0.f, sb = 0.f;
        #pragma unroll
        for (int nt = 0; nt < 16; nt++) {
            sa += ex2(S[nt][0] - nma) + ex2(S[nt][1] - nma);
            sb += ex2(S[nt][2] - nmb) + ex2(S[nt][3] - nmb);
        }
        sa += __shfl_xor_sync(0xffffffffu, sa, 1);
        sa += __shfl_xor_sync(0xffffffffu, sa, 2);
        sb += __shfl_xor_sync(0xffffffffu, sb, 1);
        sb += __shfl_xor_sync(0xffffffffu, sb, 2);

        l_a = l_a * ex2(m_a - nma) + sa;
        l_b = l_b * ex2(m_b - nmb) + sb;
        m_a = nma;
        m_b = nmb;
    }

    const float il_a = 1.0f / l_a;
    const float il_b = 1.0f / l_b;
    const int qg = qt * BM + wrow + (lane >> 2);

    // --------------------- pass 2: attn write + O = P@V --------------------
    float O[16][4];
    #pragma unroll
    for (int nt = 0; nt < 16; nt++)
        #pragma unroll
        for (int j = 0; j < 4; j++) O[nt][j] = 0.f;

    for (int kt = 0; kt < 16; kt++) {
        __syncthreads();
        #pragma unroll
        for (int i = tid; i < BN * 16; i += 256) {
            int r = i >> 4, c = (i & 15) << 3;
            *reinterpret_cast<uint4*>(sK + r * LDSH + c) =
                *reinterpret_cast<const uint4*>(Kg + ((size_t)(kt * BN + r)) * HD + c);
            *reinterpret_cast<uint4*>(sV + r * LDSH + c) =
                *reinterpret_cast<const uint4*>(Vg + ((size_t)(kt * BN + r)) * HD + c);
        }
        __syncthreads();

        float S[16][4];
        #pragma unroll
        for (int nt = 0; nt < 16; nt++)
            #pragma unroll
            for (int j = 0; j < 4; j++) S[nt][j] = 0.f;

        #pragma unroll 1
        for (int k2 = 0; k2 < 8; k2++) {
            unsigned a0, a1, a2, a3;
            ldmx4(a0, a1, a2, a3, sQ + aRow * LDSH + (k2 << 4) + aCol);
            #pragma unroll
            for (int n2 = 0; n2 < 8; n2++) {
                unsigned b0, b1, b2, b3;
                ldmx4(b0, b1, b2, b3,
                      sK + ((n2 << 4) + bRowOff) * LDSH + (k2 << 4) + bColOff);
                mma16816(S[2 * n2],     a0, a1, a2, a3, b0, b1);
                mma16816(S[2 * n2 + 1], a0, a1, a2, a3, b2, b3);
            }
        }

        // P = exp2(S - m); write normalized attention; keep P for PV mma
        #pragma unroll
        for (int nt = 0; nt < 16; nt++) {
            float p0 = ex2(S[nt][0] - m_a);
            float p1 = ex2(S[nt][1] - m_a);
            float p2 = ex2(S[nt][2] - m_b);
            float p3 = ex2(S[nt][3] - m_b);
            if (attn) {
                size_t col = (size_t)kt * BN + (nt << 3) + ((lane & 3) << 1);
                *reinterpret_cast<float2*>(attn + ((size_t)b * SEQ + qg) * SEQ + col) =
                    make_float2(p0 * il_a, p1 * il_a);
                *reinterpret_cast<float2*>(attn + ((size_t)b * SEQ + qg + 8) * SEQ + col) =
                    make_float2(p2 * il_b, p3 * il_b);
            }
            S[nt][0] = p0; S[nt][1] = p1; S[nt][2] = p2; S[nt][3] = p3;
        }

        // O += P @ V  (A from P fragments, B from V via ldmatrix.trans)
        #pragma unroll
        for (int k2 = 0; k2 < 8; k2++) {
            unsigned a0 = packh2(S[2 * k2][0],     S[2 * k2][1]);
            unsigned a1 = packh2(S[2 * k2][2],     S[2 * k2][3]);
            unsigned a2 = packh2(S[2 * k2 + 1][0], S[2 * k2 + 1][1]);
            unsigned a3 = packh2(S[2 * k2 + 1][2], S[2 * k2 + 1][3]);
            #pragma unroll
            for (int d2 = 0; d2 < 8; d2++) {
                unsigned b0, b1, b2, b3;
                ldmx4t(b0, b1, b2, b3,
                       sV + ((k2 << 4) + vRowOff) * LDSH + (d2 << 4) + vColOff);
                mma16816(O[2 * d2],     a0, a1, a2, a3, b0, b1);
                mma16816(O[2 * d2 + 1], a0, a1, a2, a3, b2, b3);
            }
        }
    }

    if (ctx) {
        #pragma unroll
        for (int nt = 0; nt < 16; nt++) {
            int col = (nt << 3) + ((lane & 3) << 1);
            *reinterpret_cast<float2*>(ctx + ((size_t)b * SEQ + qg) * HD + col) =
                make_float2(O[nt][0] * il_a, O[nt][1] * il_a);
            *reinterpret_cast<float2*>(ctx + ((size_t)b * SEQ + qg + 8) * HD + col) =
                make_float2(O[nt][2] * il_b, O[nt][3] * il_b);
        }
    }
}

// ---------------------------------------------------------------------------
extern "C" void kernel_launch(void* const* d_in, const int* in_sizes, int n_in,
                              void* d_out, int out_size) {
    const float* q = (const float*)d_in[0];
    const float* k = (const float*)d_in[1];
    const float* v = (const float*)d_in[2];
    float* out = (float*)d_out;

    const size_t CTXN = (size_t)BATCH * SEQ * HD;   // 4,194,304
    const size_t ATTN = (size_t)BATCH * SEQ * SEQ;  // 67,108,864
    float* ctx = nullptr;
    float* attn = nullptr;
    if ((size_t)out_size >= CTXN + ATTN) { ctx = out; attn = out + CTXN; }
    else if ((size_t)out_size == ATTN)   { attn = out; }
    else                                 { ctx = out; }

    // fold 1/sqrt(D) * log2(e) into Q so softmax runs in base-2 (exact identity)
    const float QSCALE = 0.08838834764831845f * 1.4426950408889634f;
    const int n4 = BATCH * SEQ * HD / 4;  // 1,048,576
    cvt_kernel<<<n4 / 256, 256>>>(q, 0, n4, QSCALE);
    cvt_kernel<<<n4 / 256, 256>>>(k, 1, n4, 1.0f);
    cvt_kernel<<<n4 / 256, 256>>>(v, 2, n4, 1.0f);

    const int smem_bytes = 3 * BM * LDSH * (int)sizeof(__half);  // 104,448
    cudaFuncSetAttribute(attn_kernel, cudaFuncAttributeMaxDynamicSharedMemorySize, smem_bytes);
    dim3 grid(SEQ / BM, BATCH);
    attn_kernel<<<grid, 256, smem_bytes>>>(ctx, attn);
}